// round 14
// baseline (speedup 1.0000x reference)
#include <cuda_runtime.h>
#include <cuda_fp16.h>
#include <math.h>
#include <stdint.h>

// ---------------- problem constants ----------------
#define S_LEN 2048
#define HID   3584
#define NH    28
#define NKV   4
#define HD    128
#define NQD   (NH*HD)    // 3584
#define NKD   (NKV*HD)   // 512
#define GRP   (NH/NKV)   // 7
#define NQKV  (NQD + 2*NKD)  // 4608

// ---------------- scratch (device globals; no allocs allowed) ----------------
__device__ float g_bias[NQKV];

__device__ __align__(16) __half g_hs16[S_LEN * HID];
__device__ __align__(16) __half g_ctx16[S_LEN * NQD];
__device__ __align__(16) __half g_q16h[S_LEN * NQD], g_q16l[S_LEN * NQD];
__device__ __align__(16) __half g_k16[S_LEN * NKD];
__device__ __align__(16) __half g_v16[S_LEN * NKD];
__device__ __align__(16) __half g_w16[(size_t)NQKV * HID];
__device__ __align__(16) __half g_wo16[(size_t)HID * NQD];

// ---------------- helpers ----------------
__device__ __forceinline__ uint32_t smem_u32(const void* p) {
    uint32_t a;
    asm("{ .reg .u64 t; cvta.to.shared.u64 t, %1; cvt.u32.u64 %0, t; }" : "=r"(a) : "l"(p));
    return a;
}

__device__ __forceinline__ void cp_async16(uint32_t dst, const void* src) {
    asm volatile("cp.async.cg.shared.global [%0], [%1], 16;" :: "r"(dst), "l"(src) : "memory");
}

__device__ __forceinline__ void ldm_x4(uint32_t* r, uint32_t addr) {
    asm volatile("ldmatrix.sync.aligned.m8n8.x4.shared.b16 {%0,%1,%2,%3}, [%4];"
                 : "=r"(r[0]), "=r"(r[1]), "=r"(r[2]), "=r"(r[3]) : "r"(addr));
}

__device__ __forceinline__ void ldm_x4_t(uint32_t* r, uint32_t addr) {
    asm volatile("ldmatrix.sync.aligned.m8n8.x4.trans.shared.b16 {%0,%1,%2,%3}, [%4];"
                 : "=r"(r[0]), "=r"(r[1]), "=r"(r[2]), "=r"(r[3]) : "r"(addr));
}

__device__ __forceinline__ void mma_f16(float* c, const uint32_t* a, const uint32_t* b) {
    asm volatile(
        "mma.sync.aligned.m16n8k16.row.col.f32.f16.f16.f32 "
        "{%0,%1,%2,%3}, {%4,%5,%6,%7}, {%8,%9}, {%0,%1,%2,%3};"
        : "+f"(c[0]), "+f"(c[1]), "+f"(c[2]), "+f"(c[3])
        : "r"(a[0]), "r"(a[1]), "r"(a[2]), "r"(a[3]), "r"(b[0]), "r"(b[1]));
}

__device__ __forceinline__ uint32_t pack_h2(float a, float b) {
    __half2 h = __floats2half2_rn(a, b);
    return *(uint32_t*)&h;
}

__device__ __forceinline__ float fexp2(float x) {
    float r;
    asm("ex2.approx.f32 %0, %1;" : "=f"(r) : "f"(x));
    return r;
}

// ---------------- convert kernels ----------------
__global__ void conv_h_kernel(const float4* __restrict__ X, __half2* __restrict__ H, int n4) {
    int i = blockIdx.x * 256 + threadIdx.x;
    if (i >= n4) return;
    float4 x = X[i];
    H[2*i]   = __floats2half2_rn(x.x, x.y);
    H[2*i+1] = __floats2half2_rn(x.z, x.w);
}

// W [K,N] fp32 row-major -> T [N,K] fp16 (single). Tile 32n x 64k, block (32,8).
__global__ void tsplit2h_kernel(const float* __restrict__ W, __half* __restrict__ T,
                                int K, int N) {
    __shared__ float t[64][33];
    int n0 = blockIdx.x * 32, k0 = blockIdx.y * 64;
    int tx = threadIdx.x, ty = threadIdx.y;
#pragma unroll
    for (int i = 0; i < 8; i++) {
        int k = i * 8 + ty;
        t[k][tx] = W[(size_t)(k0 + k) * N + n0 + tx];
    }
    __syncthreads();
#pragma unroll
    for (int i = 0; i < 4; i++) {
        int n = i * 8 + ty;
        __half2 hp = __floats2half2_rn(t[2 * tx][n], t[2 * tx + 1][n]);
        *(__half2*)(T + (size_t)(n0 + n) * K + k0 + 2 * tx) = hp;
    }
}

__global__ void concat_bias_kernel(const float* __restrict__ bq, const float* __restrict__ bk,
                                   const float* __restrict__ bv, float* __restrict__ b) {
    int i = blockIdx.x * 256 + threadIdx.x;
    if (i < NQD) b[i] = bq[i];
    else if (i < NQD + NKD) b[i] = bk[i - NQD];
    else if (i < NQKV) b[i] = bv[i - NQD - NKD];
}

// ---------------- GEMM tiling constants ----------------
#define GBK 32
#define ROWP 40
#define STG_TILE (128*ROWP*2)          // 10240 B per operand tile
#define STG1_BYTES (2*STG_TILE)        // 20480 B per stage (A, B)
#define GEMM1_SMEM (3*STG1_BYTES)      // 61440 B (3 stages)
#define EP_STRIDE 132
#define FUSED_SMEM (128*EP_STRIDE*4)   // 67584 B (epilogue staging; > pipeline bytes)

// ---------------- GEMM mainloop (shared by both kernels) ----------------
struct GemmCore {
    uint32_t sb;
    int tid, lane, warp, wm, wn, row0, col0;
    float acc[4][4][4];

    __device__ __forceinline__ void init(uint32_t sb_, int row0_, int col0_) {
        sb = sb_;
        tid = threadIdx.x; lane = tid & 31; warp = tid >> 5;
        wm = (warp >> 2) * 64; wn = (warp & 3) * 32;
        row0 = row0_; col0 = col0_;
#pragma unroll
        for (int mt = 0; mt < 4; mt++)
#pragma unroll
            for (int nt = 0; nt < 4; nt++)
#pragma unroll
                for (int i = 0; i < 4; i++) acc[mt][nt][i] = 0.f;
    }

    __device__ __forceinline__ void issue_load(const __half* A, const __half* B,
                                               int K, int stage, int kb) {
        uint32_t sbase = sb + stage * STG1_BYTES;
#pragma unroll
        for (int tile = 0; tile < 2; tile++) {
            const __half* src = (tile == 0) ? A : B;
            int gbase = (tile == 0) ? row0 : col0;
#pragma unroll
            for (int j = 0; j < 2; j++) {
                int s = j * 256 + tid;
                int row = s >> 2;
                int c = (s & 3) << 3;
                const void* g = src + (size_t)(gbase + row) * K + kb + c;
                uint32_t dst = sbase + tile * STG_TILE + (row * ROWP + c) * 2;
                cp_async16(dst, g);
            }
        }
        asm volatile("cp.async.commit_group;" ::: "memory");
    }

    __device__ __forceinline__ void run(const __half* A, const __half* B, int K) {
        const int NI = K / GBK;
        issue_load(A, B, K, 0, 0);
        issue_load(A, B, K, 1, GBK);
        int stage = 0;
        for (int i = 0; i < NI; i++) {
            if (i + 1 < NI) {
                asm volatile("cp.async.wait_group 1;" ::: "memory");
            } else {
                asm volatile("cp.async.wait_group 0;" ::: "memory");
            }
            __syncthreads();
            if (i + 2 < NI) {
                int nstage = stage + 2; if (nstage >= 3) nstage -= 3;
                issue_load(A, B, K, nstage, (i + 2) * GBK);
            }
            const uint32_t sa = sb + stage * STG1_BYTES;
#pragma unroll
            for (int ks = 0; ks < 2; ks++) {
                uint32_t bh[4][2];
#pragma unroll
                for (int np = 0; np < 2; np++) {
                    uint32_t addr = sa + STG_TILE +
                        ((wn + np * 16 + ((lane >> 4) << 3) + (lane & 7)) * ROWP
                         + ks * 16 + (((lane >> 3) & 1) << 3)) * 2;
                    ldm_x4(&bh[np * 2][0], addr);
                }
#pragma unroll
                for (int mt = 0; mt < 4; mt++) {
                    uint32_t ah[4];
                    uint32_t addr = sa +
                        ((wm + mt * 16 + (lane & 15)) * ROWP + ks * 16 + ((lane >> 4) << 3)) * 2;
                    ldm_x4(ah, addr);
#pragma unroll
                    for (int nt = 0; nt < 4; nt++) {
                        mma_f16(acc[mt][nt], ah, bh[nt]);
                    }
                }
            }
            if (++stage == 3) stage = 0;
        }
    }
};

// ---------------- O-projection GEMM (fp32 out) ----------------
__global__ __launch_bounds__(256, 2)
void gemm_f16_1t(const __half* __restrict__ A, const __half* __restrict__ B,
                 float* __restrict__ C, int K, int Ntot) {
    extern __shared__ char smem[];
    GemmCore g;
    g.init(smem_u32(smem), blockIdx.y * 128, blockIdx.x * 128);
    g.run(A, B, K);

#pragma unroll
    for (int mt = 0; mt < 4; mt++) {
#pragma unroll
        for (int nt = 0; nt < 4; nt++) {
            int r = g.row0 + g.wm + mt * 16 + (g.lane >> 2);
            int cidx = g.col0 + g.wn + nt * 8 + ((g.lane & 3) << 1);
            float2* p0 = (float2*)(C + (size_t)r * Ntot + cidx);
            float2* p1 = (float2*)(C + (size_t)(r + 8) * Ntot + cidx);
            *p0 = make_float2(g.acc[mt][nt][0], g.acc[mt][nt][1]);
            *p1 = make_float2(g.acc[mt][nt][2], g.acc[mt][nt][3]);
        }
    }
}

// ---------------- fused QKV GEMM + bias + mROPE + fp16 emit ----------------
// Each CTA covers exactly one head (col0 = head*128). Rope pairs (d, d+64) stay in-tile.
__global__ __launch_bounds__(256, 2)
void gemm_qkv_rope(const __half* __restrict__ A, const __half* __restrict__ B,
                   const float* __restrict__ bias,
                   const float* __restrict__ cosp, const float* __restrict__ sinp,
                   __half* __restrict__ qh, __half* __restrict__ ql,
                   __half* __restrict__ k16, __half* __restrict__ v16) {
    extern __shared__ char smem[];
    GemmCore g;
    g.init(smem_u32(smem), blockIdx.y * 128, blockIdx.x * 128);
    g.run(A, B, HID);

    // ---- stage acc tile to smem (fp32, stride 132 floats) ----
    __syncthreads();   // all warps done reading pipeline smem
    float* smf = (float*)smem;
#pragma unroll
    for (int mt = 0; mt < 4; mt++) {
#pragma unroll
        for (int nt = 0; nt < 4; nt++) {
            int r = g.wm + mt * 16 + (g.lane >> 2);
            int c = g.wn + nt * 8 + ((g.lane & 3) << 1);
            *(float2*)&smf[r * EP_STRIDE + c]       = make_float2(g.acc[mt][nt][0], g.acc[mt][nt][1]);
            *(float2*)&smf[(r + 8) * EP_STRIDE + c] = make_float2(g.acc[mt][nt][2], g.acc[mt][nt][3]);
        }
    }
    __syncthreads();

    // ---- bias + mROPE + fp16 emit ----
    const int head = blockIdx.x;                 // 0..35
    const int d  = threadIdx.x & 63;             // 0..63
    const int rg = threadIdx.x >> 6;             // 0..3
    const int sec = (d < 16) ? 0 : ((d < 40) ? 1 : 2);
    const int SH = S_LEN * HD;
    const float qscale = 0.08838834764831845f * 1.4426950408889634f; // 1/sqrt(128)*log2e

    const float b1 = bias[g.col0 + d];
    const float b2 = bias[g.col0 + d + 64];

    if (head < NH) {
        // q head: rope + scale, hi/lo split
#pragma unroll 1
        for (int i = 0; i < 32; i++) {
            int r = rg * 32 + i;
            int s = g.row0 + r;
            float x1 = smf[r * EP_STRIDE + d] + b1;
            float x2 = smf[r * EP_STRIDE + d + 64] + b2;
            float c1 = cosp[sec * SH + s * HD + d];
            float s1 = sinp[sec * SH + s * HD + d];
            float c2 = cosp[sec * SH + s * HD + d + 64];
            float s2 = sinp[sec * SH + s * HD + d + 64];
            float y1 = (x1 * c1 - x2 * s1) * qscale;
            float y2 = (x2 * c2 + x1 * s2) * qscale;
            size_t o = (size_t)s * NQD + head * HD;
            __half h1 = __float2half_rn(y1), h2 = __float2half_rn(y2);
            qh[o + d]      = h1;
            qh[o + d + 64] = h2;
            ql[o + d]      = __float2half_rn(y1 - __half2float(h1));
            ql[o + d + 64] = __float2half_rn(y2 - __half2float(h2));
        }
    } else if (head < NH + NKV) {
        int kvi = head - NH;
#pragma unroll 1
        for (int i = 0; i < 32; i++) {
            int r = rg * 32 + i;
            int s = g.row0 + r;
            float x1 = smf[r * EP_STRIDE + d] + b1;
            float x2 = smf[r * EP_STRIDE + d + 64] + b2;
            float c1 = cosp[sec * SH + s * HD + d];
            float s1 = sinp[sec * SH + s * HD + d];
            float c2 = cosp[sec * SH + s * HD + d + 64];
            float s2 = sinp[sec * SH + s * HD + d + 64];
            size_t o = (size_t)s * NKD + kvi * HD;
            k16[o + d]      = __float2half_rn(x1 * c1 - x2 * s1);
            k16[o + d + 64] = __float2half_rn(x2 * c2 + x1 * s2);
        }
    } else {
        int kvi = head - NH - NKV;
#pragma unroll 1
        for (int i = 0; i < 32; i++) {
            int r = rg * 32 + i;
            int s = g.row0 + r;
            size_t o = (size_t)s * NKD + kvi * HD;
            v16[o + d]      = __float2half_rn(smf[r * EP_STRIDE + d] + b1);
            v16[o + d + 64] = __float2half_rn(smf[r * EP_STRIDE + d + 64] + b2);
        }
    }
}

// ---------------- attention: fp16 mma flash, BN=64, QK 2-term / PV 1-term ----------------
#define ATP 136
#define AT_ROWB (ATP*2)              // 272 B/row
#define AQ_TILE (128*AT_ROWB)        // 34816
#define KV_TILE (64*AT_ROWB)         // 17408
#define KV_STG  (2*KV_TILE)          // 34816 (K, V)
#define AQ_H 0
#define AQ_L AQ_TILE
#define AKV  (2*AQ_TILE)
#define ATTN_SMEM (AKV + 2*KV_STG)   // 139264 B

__global__ __launch_bounds__(256)
void attn_mma(const __half* __restrict__ qh, const __half* __restrict__ ql,
              const __half* __restrict__ k16, const __half* __restrict__ v16,
              __half* __restrict__ ctx16) {
    extern __shared__ char smem[];
    const uint32_t sb = smem_u32(smem);
    const int tid = threadIdx.x;
    const int lane = tid & 31;
    const int warp = tid >> 5;           // 0..7
    const int h = blockIdx.y;
    const int kvh = h / GRP;
    const int r0 = blockIdx.x * 128;

#pragma unroll
    for (int j = 0; j < 8; j++) {
        int idx = j * 256 + tid;
        int row = idx >> 4, c = idx & 15;
        size_t g = (size_t)(r0 + row) * NQD + h * HD + c * 8;
        uint32_t so = row * AT_ROWB + c * 16;
        cp_async16(sb + AQ_H + so, qh + g);
        cp_async16(sb + AQ_L + so, ql + g);
    }
    asm volatile("cp.async.commit_group;" ::: "memory");

    auto issue_kv = [&](int stage, int kt) {
        uint32_t base = sb + AKV + stage * KV_STG;
#pragma unroll
        for (int j = 0; j < 4; j++) {
            int idx = j * 256 + tid;
            int row = idx >> 4, c = idx & 15;
            size_t g = (size_t)(kt + row) * NKD + kvh * HD + c * 8;
            uint32_t so = row * AT_ROWB + c * 16;
            cp_async16(base + 0 * KV_TILE + so, k16 + g);
            cp_async16(base + 1 * KV_TILE + so, v16 + g);
        }
        asm volatile("cp.async.commit_group;" ::: "memory");
    };

    issue_kv(0, 0);
    asm volatile("cp.async.wait_group 1;" ::: "memory");
    __syncthreads();

    uint32_t qfh[8][4], qfl[8][4];
#pragma unroll
    for (int kf = 0; kf < 8; kf++) {
        uint32_t off = ((warp * 16 + (lane & 15)) * ATP + kf * 16 + ((lane >> 4) << 3)) * 2;
        ldm_x4(qfh[kf], sb + AQ_H + off);
        ldm_x4(qfl[kf], sb + AQ_L + off);
    }

    float o[16][4];
#pragma unroll
    for (int nt = 0; nt < 16; nt++)
#pragma unroll
        for (int i = 0; i < 4; i++) o[nt][i] = 0.f;
    float m0 = -INFINITY, m1 = -INFINITY, l0 = 0.f, l1 = 0.f;

    const int NI = S_LEN / 64;            // 32

    for (int it = 0; it < NI; it++) {
        asm volatile("cp.async.wait_group 0;" ::: "memory");
        __syncthreads();
        if (it + 1 < NI) issue_kv((it + 1) & 1, (it + 1) * 64);

        const uint32_t sk = sb + AKV + (it & 1) * KV_STG;

        float s[8][4];
#pragma unroll
        for (int nt = 0; nt < 8; nt++)
#pragma unroll
            for (int i = 0; i < 4; i++) s[nt][i] = 0.f;

#pragma unroll
        for (int kf = 0; kf < 8; kf++) {
            uint32_t kb[8][2];
#pragma unroll
            for (int np = 0; np < 4; np++) {
                uint32_t addr = sk +
                    ((np * 16 + ((lane >> 4) << 3) + (lane & 7)) * ATP
                     + kf * 16 + (((lane >> 3) & 1) << 3)) * 2;
                ldm_x4(&kb[np * 2][0], addr);
            }
#pragma unroll
            for (int nt = 0; nt < 8; nt++) {
                mma_f16(s[nt], qfh[kf], kb[nt]);
                mma_f16(s[nt], qfl[kf], kb[nt]);
            }
        }

        float mx0 = -INFINITY, mx1 = -INFINITY;
#pragma unroll
        for (int nt = 0; nt < 8; nt++) {
            mx0 = fmaxf(mx0, fmaxf(s[nt][0], s[nt][1]));
            mx1 = fmaxf(mx1, fmaxf(s[nt][2], s[nt][3]));
        }
        mx0 = fmaxf(mx0, __shfl_xor_sync(0xffffffffu, mx0, 1));
        mx0 = fmaxf(mx0, __shfl_xor_sync(0xffffffffu, mx0, 2));
        mx1 = fmaxf(mx1, __shfl_xor_sync(0xffffffffu, mx1, 1));
        mx1 = fmaxf(mx1, __shfl_xor_sync(0xffffffffu, mx1, 2));

        float nm0 = fmaxf(m0, mx0), nm1 = fmaxf(m1, mx1);
        float c0 = fexp2(m0 - nm0), c1 = fexp2(m1 - nm1);
        m0 = nm0; m1 = nm1;

        float sum0 = 0.f, sum1 = 0.f;
#pragma unroll
        for (int nt = 0; nt < 8; nt++) {
            s[nt][0] = fexp2(s[nt][0] - nm0);
            s[nt][1] = fexp2(s[nt][1] - nm0);
            s[nt][2] = fexp2(s[nt][2] - nm1);
            s[nt][3] = fexp2(s[nt][3] - nm1);
            sum0 += s[nt][0] + s[nt][1];
            sum1 += s[nt][2] + s[nt][3];
        }
        sum0 += __shfl_xor_sync(0xffffffffu, sum0, 1);
        sum0 += __shfl_xor_sync(0xffffffffu, sum0, 2);
        sum1 += __shfl_xor_sync(0xffffffffu, sum1, 1);
        sum1 += __shfl_xor_sync(0xffffffffu, sum1, 2);
        l0 = l0 * c0 + sum0;
        l1 = l1 * c1 + sum1;

#pragma unroll
        for (int nt = 0; nt < 16; nt++) {
            o[nt][0] *= c0; o[nt][1] *= c0;
            o[nt][2] *= c1; o[nt][3] *= c1;
        }

#pragma unroll
        for (int kf = 0; kf < 4; kf++) {
            uint32_t ah[4];
#pragma unroll
            for (int half = 0; half < 2; half++) {
                int nt = 2 * kf + half;
                ah[2 * half]     = pack_h2(s[nt][0], s[nt][1]);
                ah[2 * half + 1] = pack_h2(s[nt][2], s[nt][3]);
            }
#pragma unroll
            for (int np = 0; np < 8; np++) {
                uint32_t vb[4];
                uint32_t addr = sk + KV_TILE +
                    ((kf * 16 + (lane & 15)) * ATP + np * 16 + ((lane >> 4) << 3)) * 2;
                ldm_x4_t(vb, addr);
                mma_f16(o[2 * np],     ah, &vb[0]);
                mma_f16(o[2 * np + 1], ah, &vb[2]);
            }
        }
    }

    float inv0 = 1.f / l0, inv1 = 1.f / l1;
    int r_lo = r0 + warp * 16 + (lane >> 2);
    int r_hi = r_lo + 8;
#pragma unroll
    for (int nt = 0; nt < 16; nt++) {
        int col = h * HD + nt * 8 + ((lane & 3) << 1);
        *(__half2*)(ctx16 + (size_t)r_lo * NQD + col) =
            __floats2half2_rn(o[nt][0] * inv0, o[nt][1] * inv0);
        *(__half2*)(ctx16 + (size_t)r_hi * NQD + col) =
            __floats2half2_rn(o[nt][2] * inv1, o[nt][3] * inv1);
    }
}

// ---------------- launch ----------------
extern "C" void kernel_launch(void* const* d_in, const int* in_sizes, int n_in,
                              void* d_out, int out_size) {
    const float* hs   = (const float*)d_in[0];
    const float* cosp = (const float*)d_in[1];
    const float* sinp = (const float*)d_in[2];
    const float* Wq   = (const float*)d_in[3];
    const float* bq   = (const float*)d_in[4];
    const float* Wk   = (const float*)d_in[5];
    const float* bk   = (const float*)d_in[6];
    const float* Wv   = (const float*)d_in[7];
    const float* bv   = (const float*)d_in[8];
    const float* Wo   = (const float*)d_in[9];
    float* out = (float*)d_out;

    float* bias_p;
    cudaGetSymbolAddress((void**)&bias_p, g_bias);

    __half *hs16, *w16, *wo16, *ctx16, *q16h, *q16l, *k16, *v16;
    cudaGetSymbolAddress((void**)&hs16,  g_hs16);
    cudaGetSymbolAddress((void**)&ctx16, g_ctx16);
    cudaGetSymbolAddress((void**)&w16,   g_w16);  cudaGetSymbolAddress((void**)&wo16, g_wo16);
    cudaGetSymbolAddress((void**)&q16h,  g_q16h); cudaGetSymbolAddress((void**)&q16l, g_q16l);
    cudaGetSymbolAddress((void**)&k16,   g_k16);  cudaGetSymbolAddress((void**)&v16,  g_v16);

    cudaFuncSetAttribute(gemm_f16_1t,   cudaFuncAttributeMaxDynamicSharedMemorySize, GEMM1_SMEM);
    cudaFuncSetAttribute(gemm_qkv_rope, cudaFuncAttributeMaxDynamicSharedMemorySize, FUSED_SMEM);
    cudaFuncSetAttribute(attn_mma,      cudaFuncAttributeMaxDynamicSharedMemorySize, ATTN_SMEM);

    // 1) input convert + weight transposes (all fp16) + bias concat
    {
        int n4 = S_LEN * HID / 4;
        conv_h_kernel<<<(n4 + 255) / 256, 256>>>((const float4*)hs, (__half2*)hs16, n4);
    }
    {
        dim3 blk(32, 8);
        tsplit2h_kernel<<<dim3(NQD / 32, HID / 64), blk>>>(Wq, w16, HID, NQD);
        tsplit2h_kernel<<<dim3(NKD / 32, HID / 64), blk>>>(Wk, w16 + (size_t)NQD * HID, HID, NKD);
        tsplit2h_kernel<<<dim3(NKD / 32, HID / 64), blk>>>(Wv, w16 + (size_t)(NQD + NKD) * HID, HID, NKD);
        tsplit2h_kernel<<<dim3(HID / 32, NQD / 64), blk>>>(Wo, wo16, NQD, HID);
        concat_bias_kernel<<<(NQKV + 255) / 256, 256>>>(bq, bk, bv, bias_p);
    }

    // 2) fused QKV projection + bias + mROPE + fp16 emit
    gemm_qkv_rope<<<dim3(NQKV / 128, S_LEN / 128), 256, FUSED_SMEM>>>(
        hs16, w16, bias_p, cosp, sinp, q16h, q16l, k16, v16);

    // 3) attention -> ctx (single fp16)
    {
        dim3 grid(S_LEN / 128, NH);
        attn_mma<<<grid, 256, ATTN_SMEM>>>(q16h, q16l, k16, v16, ctx16);
    }

    // 4) output projection (fp16 1-term)
    gemm_f16_1t<<<dim3(HID / 128, S_LEN / 128), 256, GEMM1_SMEM>>>(ctx16, wo16, out, NQD, HID);
}